// round 2
// baseline (speedup 1.0000x reference)
#include <cuda_runtime.h>
#include <cstdint>

#define HID   128
#define NEDGE 800000
#define NNODE 50000

// ---- scratch (static __device__ arrays; allocation-free) ----
__device__ float g_Ha[NNODE * HID];   // h @ Wa   (25.6 MB)
__device__ float g_Hb[NNODE * HID];   // h @ Wb   (25.6 MB)
__device__ float g_a[NEDGE];          // per-edge logits (3.2 MB)
__device__ int   g_row[NEDGE];
__device__ int   g_col[NEDGE];
__device__ int   g_is64;
__device__ float g_pm[256];           // partial max
__device__ float g_ps[256];           // partial sum
__device__ float g_stats[2];          // {max, 1/sum}

// ---- packed f32x2 helpers (FFMA2 only reachable via PTX) ----
__device__ __forceinline__ unsigned long long pk(float x, float y) {
    unsigned long long r;
    asm("mov.b64 %0, {%1, %2};" : "=l"(r) : "f"(x), "f"(y));
    return r;
}
__device__ __forceinline__ unsigned long long pk1(float x) { return pk(x, x); }
__device__ __forceinline__ void fma2(unsigned long long& d, unsigned long long a, unsigned long long b) {
    asm("fma.rn.f32x2 %0, %1, %2, %0;" : "+l"(d) : "l"(a), "l"(b));
}
__device__ __forceinline__ float2 upk(unsigned long long v) {
    float2 r;
    asm("mov.b64 {%0, %1}, %2;" : "=f"(r.x), "=f"(r.y) : "l"(v));
    return r;
}

// ============================================================
// Kernel 0a: detect edge_index dtype (int32 vs int64).
// int64 values are 0..49999 -> odd int32 words are all zero.
// int32 random values cannot produce 64 consecutive zero odd words.
// ============================================================
__global__ void detect(const int* __restrict__ ei32) {
    if (threadIdx.x == 0 && blockIdx.x == 0) {
        int orv = 0;
        for (int i = 0; i < 64; i++) orv |= ei32[2 * i + 1];
        g_is64 = (orv == 0) ? 1 : 0;
    }
}

// ============================================================
// Kernel 0b: convert edge_index to clamped int32 row/col arrays.
// ============================================================
__global__ void __launch_bounds__(256) convert(const void* __restrict__ eiraw) {
    int e = blockIdx.x * 256 + threadIdx.x;
    if (e >= NEDGE) return;
    int row, col;
    if (g_is64) {
        const long long* p = (const long long*)eiraw;
        row = (int)p[e];
        col = (int)p[NEDGE + e];
    } else {
        const int* p = (const int*)eiraw;
        row = p[e];
        col = p[NEDGE + e];
    }
    g_row[e] = min(max(row, 0), NNODE - 1);
    g_col[e] = min(max(col, 0), NNODE - 1);
}

// ============================================================
// Kernel 1: node GEMM  Ha = h@Wa, Hb = h@Wb  (fused N=256)
// Block: 256 threads (8 warps), 4 nodes per warp.
// smem: Wab as f32x2 pairs [128 k][128 pairs] = 128KB, + h staging 16KB.
// ============================================================
__global__ void __launch_bounds__(256, 1) node_gemm(const float* __restrict__ h,
                                                    const float* __restrict__ W1) {
    extern __shared__ char smraw[];
    unsigned long long* wab = (unsigned long long*)smraw;        // [128][128] pairs
    float* hst = (float*)(smraw + 131072);                        // [8][4][128]

    int tid = threadIdx.x;
    // pair p < 64  -> Wa cols {2p, 2p+1};  p >= 64 -> Wb cols {2(p-64), ...}
    for (int idx = tid; idx < 128 * 128; idx += 256) {
        int k = idx >> 7, p = idx & 127;
        const float* src = (p < 64) ? &W1[k * HID + 2 * p]
                                    : &W1[(HID + k) * HID + 2 * (p - 64)];
        float2 v = *(const float2*)src;
        wab[idx] = pk(v.x, v.y);
    }
    __syncthreads();

    int w = tid >> 5, l = tid & 31;
    int group = blockIdx.x * 8 + w;
    if (group * 4 >= NNODE) return;
    int n0 = group * 4;

    float* hw = hst + w * 4 * HID;
#pragma unroll
    for (int e = 0; e < 4; e++) {
        float4 v = *(const float4*)&h[(size_t)(n0 + e) * HID + 4 * l];
        *(float4*)&hw[e * HID + 4 * l] = v;
    }
    __syncwarp();

    unsigned long long acc[4][4];
#pragma unroll
    for (int e = 0; e < 4; e++)
#pragma unroll
        for (int j = 0; j < 4; j++) acc[e][j] = 0ULL;

    for (int k = 0; k < HID; k += 2) {
        unsigned long long w0[4], w1[4];
#pragma unroll
        for (int j = 0; j < 4; j++) {
            w0[j] = wab[k * 128 + l + 32 * j];
            w1[j] = wab[(k + 1) * 128 + l + 32 * j];
        }
#pragma unroll
        for (int e = 0; e < 4; e++) {
            float2 hv = *(float2*)&hw[e * HID + k];
            unsigned long long hx = pk1(hv.x), hy = pk1(hv.y);
#pragma unroll
            for (int j = 0; j < 4; j++) {
                fma2(acc[e][j], hx, w0[j]);
                fma2(acc[e][j], hy, w1[j]);
            }
        }
    }

#pragma unroll
    for (int e = 0; e < 4; e++)
#pragma unroll
        for (int j = 0; j < 4; j++) {
            int p = l + 32 * j;
            float2 v = upk(acc[e][j]);
            if (p < 64)
                *(float2*)&g_Ha[(size_t)(n0 + e) * HID + 2 * p] = v;
            else
                *(float2*)&g_Hb[(size_t)(n0 + e) * HID + 2 * (p - 64)] = v;
        }
}

// ============================================================
// Kernel 2: edge GEMM + fused epilogue -> per-edge logit a[e]
//   pre = ea@Wc + Ha[row] + Hb[col] + b1
//   a   = leaky_relu( elu(pre) . W2 + b2, 0.2 )
// Block: 256 threads (8 warps), 8 edges per warp.
// ============================================================
__global__ void __launch_bounds__(256, 2) edge_att(const float* __restrict__ ea,
                                                   const float* __restrict__ W1,
                                                   const float* __restrict__ b1,
                                                   const float* __restrict__ W2,
                                                   const float* __restrict__ b2) {
    extern __shared__ char smraw[];
    unsigned long long* wcp = (unsigned long long*)smraw;   // [128][64] pairs (64KB)
    float* east = (float*)(smraw + 65536);                   // [8][8][128]   (32KB)
    float* w2s  = (float*)(smraw + 98304);                   // [128]
    float* b1s  = (float*)(smraw + 98816);                   // [128]

    int tid = threadIdx.x;
    for (int idx = tid; idx < 128 * 64; idx += 256) {
        int k = idx >> 6, p = idx & 63;
        float2 v = *(const float2*)&W1[(2 * HID + k) * HID + 2 * p];
        wcp[idx] = pk(v.x, v.y);
    }
    if (tid < 128) {
        w2s[tid] = W2[tid];
        b1s[tid] = b1[tid];
    }
    __syncthreads();

    int w = tid >> 5, l = tid & 31;
    int e0 = (blockIdx.x * 8 + w) * 8;
    float* est = east + w * 8 * HID;

#pragma unroll
    for (int e = 0; e < 8; e++) {
        float4 v = *(const float4*)&ea[(size_t)(e0 + e) * HID + 4 * l];
        *(float4*)&est[e * HID + 4 * l] = v;
    }
    __syncwarp();

    unsigned long long acc[8][2];
#pragma unroll
    for (int e = 0; e < 8; e++) { acc[e][0] = 0ULL; acc[e][1] = 0ULL; }

    for (int k = 0; k < HID; k += 2) {
        unsigned long long w00 = wcp[k * 64 + l];
        unsigned long long w01 = wcp[k * 64 + l + 32];
        unsigned long long w10 = wcp[(k + 1) * 64 + l];
        unsigned long long w11 = wcp[(k + 1) * 64 + l + 32];
#pragma unroll
        for (int e = 0; e < 8; e++) {
            float2 ev = *(float2*)&est[e * HID + k];
            unsigned long long ex = pk1(ev.x), ey = pk1(ev.y);
            fma2(acc[e][0], ex, w00);
            fma2(acc[e][1], ex, w01);
            fma2(acc[e][0], ey, w10);
            fma2(acc[e][1], ey, w11);
        }
    }

    float b2v = b2[0];
#pragma unroll
    for (int e = 0; e < 8; e++) {
        int ed = e0 + e;
        int row = g_row[ed];
        int col = g_col[ed];
        float partial = 0.f;
#pragma unroll
        for (int j = 0; j < 2; j++) {
            int p = l + 32 * j;
            float2 v  = upk(acc[e][j]);
            float2 ha = *(const float2*)&g_Ha[(size_t)row * HID + 2 * p];
            float2 hb = *(const float2*)&g_Hb[(size_t)col * HID + 2 * p];
            float x0 = v.x + ha.x + hb.x + b1s[2 * p];
            float x1 = v.y + ha.y + hb.y + b1s[2 * p + 1];
            float u0 = x0 > 0.f ? x0 : (__expf(x0) - 1.f);   // elu
            float u1 = x1 > 0.f ? x1 : (__expf(x1) - 1.f);
            partial += u0 * w2s[2 * p] + u1 * w2s[2 * p + 1];
        }
#pragma unroll
        for (int off = 16; off; off >>= 1)
            partial += __shfl_xor_sync(0xffffffffu, partial, off);
        if (l == 0) {
            float a = partial + b2v;
            g_a[ed] = a > 0.f ? a : 0.2f * a;                // leaky_relu 0.2
        }
    }
}

// ============================================================
// Kernels 3/4: deterministic two-stage online logsumexp
// ============================================================
__device__ __forceinline__ void merge_ms(float& m, float& s, float m2, float s2) {
    float mn = fmaxf(m, m2);
    s = s * __expf(m - mn) + s2 * __expf(m2 - mn);
    m = mn;
}

__global__ void softmax_part() {
    int gtid = blockIdx.x * 256 + threadIdx.x;
    float m = -1e30f, s = 0.f;
    for (int i = gtid; i < NEDGE; i += 256 * 256) {
        float v = g_a[i];
        if (v > m) { s = s * __expf(m - v) + 1.f; m = v; }
        else       { s += __expf(v - m); }
    }
    __shared__ float sm_[256], ss_[256];
    sm_[threadIdx.x] = m; ss_[threadIdx.x] = s;
    __syncthreads();
    for (int off = 128; off; off >>= 1) {
        if (threadIdx.x < off) {
            float mm = sm_[threadIdx.x], ssv = ss_[threadIdx.x];
            merge_ms(mm, ssv, sm_[threadIdx.x + off], ss_[threadIdx.x + off]);
            sm_[threadIdx.x] = mm; ss_[threadIdx.x] = ssv;
        }
        __syncthreads();
    }
    if (threadIdx.x == 0) { g_pm[blockIdx.x] = sm_[0]; g_ps[blockIdx.x] = ss_[0]; }
}

__global__ void softmax_final() {
    int t = threadIdx.x;
    __shared__ float sm_[256], ss_[256];
    sm_[t] = g_pm[t]; ss_[t] = g_ps[t];
    __syncthreads();
    for (int off = 128; off; off >>= 1) {
        if (t < off) {
            float mm = sm_[t], ssv = ss_[t];
            merge_ms(mm, ssv, sm_[t + off], ss_[t + off]);
            sm_[t] = mm; ss_[t] = ssv;
        }
        __syncthreads();
    }
    if (t == 0) { g_stats[0] = sm_[0]; g_stats[1] = 1.f / ss_[0]; }
}

// ============================================================
// Kernel 5: scatter  out[row] += alpha_e * h[col]   (red.v4.f32)
// Warp per 4 edges; lane handles 4 contiguous floats.
// ============================================================
__global__ void __launch_bounds__(256) scatter(const float* __restrict__ h,
                                               float* __restrict__ out) {
    int gw = (blockIdx.x * 256 + threadIdx.x) >> 5;
    int l = threadIdx.x & 31;
    float m = g_stats[0], inv = g_stats[1];
    int e0 = gw * 4;
#pragma unroll
    for (int e = 0; e < 4; e++) {
        int ed = e0 + e;
        if (ed >= NEDGE) return;
        float alpha = __expf(g_a[ed] - m) * inv;
        int row = g_row[ed];
        int col = g_col[ed];
        float4 hv = *(const float4*)&h[(size_t)col * HID + 4 * l];
        float* dst = &out[(size_t)row * HID + 4 * l];
        asm volatile("red.global.add.v4.f32 [%0], {%1, %2, %3, %4};"
                     :: "l"(dst), "f"(alpha * hv.x), "f"(alpha * hv.y),
                        "f"(alpha * hv.z), "f"(alpha * hv.w)
                     : "memory");
    }
}

// ============================================================
extern "C" void kernel_launch(void* const* d_in, const int* in_sizes, int n_in,
                              void* d_out, int out_size) {
    const float* h  = (const float*)d_in[0];
    const void*  ei = (const void*)d_in[1];
    const float* ea = (const float*)d_in[2];
    const float* W1 = (const float*)d_in[3];
    const float* b1 = (const float*)d_in[4];
    const float* W2 = (const float*)d_in[5];
    const float* b2 = (const float*)d_in[6];
    float* out = (float*)d_out;

    cudaFuncSetAttribute(node_gemm, cudaFuncAttributeMaxDynamicSharedMemorySize, 147456);
    cudaFuncSetAttribute(edge_att,  cudaFuncAttributeMaxDynamicSharedMemorySize, 99328);

    detect<<<1, 32>>>((const int*)ei);
    convert<<<(NEDGE + 255) / 256, 256>>>(ei);
    node_gemm<<<1563, 256, 147456>>>(h, W1);
    edge_att<<<12500, 256, 99328>>>(ea, W1, b1, W2, b2);
    softmax_part<<<256, 256>>>();
    softmax_final<<<1, 256>>>();
    cudaMemsetAsync(d_out, 0, (size_t)out_size * sizeof(float));
    scatter<<<25000, 256>>>(h, out);
}